// round 1
// baseline (speedup 1.0000x reference)
#include <cuda_runtime.h>

// ---------------------------------------------------------------------------
// GMMNet: per-pixel recurrent GMM block over S=8 frames.
// One thread per pixel; carry (pi[5], mu[15], rinv[5]=1/sigma) in registers.
// Weights (871 floats) live in __constant__ memory, copied in via
// graph-capturable cudaMemcpyToSymbolAsync (device-to-device).
// ---------------------------------------------------------------------------

namespace {
constexpr int Bn = 4, Sn = 8, Cn = 3, Hn = 384, Wn = 384, Kn = 5, CKn = 15;
constexpr int HWn  = Hn * Wn;          // 147456
constexpr int NPIX = Bn * HWn;         // 589824

// constant-bank layout (element offsets)
constexpr int PI_W1 = 0,   PI_B1 = 50,  PI_W2 = 55,  PI_B2 = 80;   // 5x10,5,5x5,5
constexpr int MU_W1 = 85,  MU_B1 = 430, MU_W2 = 445, MU_B2 = 670;  // 15x23,15,15x15,15
constexpr int SG_W1 = 685, SG_B1 = 800, SG_W2 = 805, SG_B2 = 830;  // 5x23,5,5x5,5
constexpr int GA_W1 = 835, GA_B1 = 860, GA_W2 = 865, GA_B2 = 870;  // 5x5,5,1x5,1
constexpr int NWTS  = 871;
}

__constant__ float cw[NWTS];

__device__ __forceinline__ float sigmoid_f(float x) {
    return __fdividef(1.0f, 1.0f + __expf(-x));
}

__global__ void __launch_bounds__(256)
gmm_kernel(const float* __restrict__ frames,   // [B,S,C,H,W]
           const float* __restrict__ mu0,      // [B,CK,H,W]
           float* __restrict__ out)             // [B,S,1,H,W]
{
    const int p = blockIdx.x * blockDim.x + threadIdx.x;
    if (p >= NPIX) return;
    const int b  = p / HWn;
    const int hw = p - b * HWn;

    // (2*pi)^(-3/2)
    const float C0 = 0.06349363593424097f;

    // carried state
    float pi[Kn], mu[CKn], ri[Kn];   // ri = 1/sigma
#pragma unroll
    for (int k = 0; k < Kn; k++) { pi[k] = 0.2f; ri[k] = 1.0f; }
#pragma unroll
    for (int i = 0; i < CKn; i++) mu[i] = mu0[(b * CKn + i) * HWn + hw];

    const float* fb = frames + (b * Sn * Cn) * HWn + hw;
    float*       ob = out    + (b * Sn)      * HWn + hw;

    for (int s = 0; s < Sn; s++) {
        float x[Cn];
#pragma unroll
        for (int c = 0; c < Cn; c++) x[c] = fb[(s * Cn + c) * HWn];

        // ---- density 1 (current mu, sigma), alpha, rho -------------------
        float alpha[Kn], rho[Kn];
#pragma unroll
        for (int k = 0; k < Kn; k++) {
            const float r  = ri[k];
            const float r2 = r * r;
            float d = 0.f;
#pragma unroll
            for (int c = 0; c < Cn; c++) {
                const float t = x[c] - mu[k * Cn + c];
                d = fmaf(t, t, d);
            }
            const float dens = C0 * r2 * r * __expf(-0.5f * d * r2);
            alpha[k] = pi[k] * dens;
            rho[k]   = alpha[k] * dens;
        }

        // ---- pi MLP: in=[pi(5), alpha(5)] -> hidden 5 (relu) -> 5, softmax
        float hp[Kn];
#pragma unroll
        for (int o = 0; o < Kn; o++) {
            float a = cw[PI_B1 + o];
#pragma unroll
            for (int i = 0; i < Kn; i++) a = fmaf(cw[PI_W1 + o * 10 + i],      pi[i],    a);
#pragma unroll
            for (int i = 0; i < Kn; i++) a = fmaf(cw[PI_W1 + o * 10 + 5 + i], alpha[i], a);
            hp[o] = fmaxf(a, 0.f);
        }
        float pin[Kn], esum = 0.f;
#pragma unroll
        for (int o = 0; o < Kn; o++) {
            float a = cw[PI_B2 + o];
#pragma unroll
            for (int i = 0; i < Kn; i++) a = fmaf(cw[PI_W2 + o * 5 + i], hp[i], a);
            pin[o] = __expf(a);
            esum  += pin[o];
        }
        const float einv = __fdividef(1.f, esum);
#pragma unroll
        for (int k = 0; k < Kn; k++) pin[k] *= einv;

        // ---- mu MLP: in=[x(3), mu(15), rho(5)] -> 15 (relu) -> 15, sigmoid
        float hm[CKn];
#pragma unroll
        for (int o = 0; o < CKn; o++) {
            const int base = MU_W1 + o * 23;
            float a = cw[MU_B1 + o];
#pragma unroll
            for (int c = 0; c < Cn; c++)  a = fmaf(cw[base + c],       x[c],  a);
#pragma unroll
            for (int i = 0; i < CKn; i++) a = fmaf(cw[base + 3 + i],   mu[i], a);
#pragma unroll
            for (int i = 0; i < Kn; i++)  a = fmaf(cw[base + 18 + i],  rho[i],a);
            hm[o] = fmaxf(a, 0.f);
        }
        float mun[CKn];
#pragma unroll
        for (int o = 0; o < CKn; o++) {
            float a = cw[MU_B2 + o];
#pragma unroll
            for (int i = 0; i < CKn; i++) a = fmaf(cw[MU_W2 + o * 15 + i], hm[i], a);
            mun[o] = sigmoid_f(a);
        }

        // ---- sigma MLP: in=[x(3), mun(15), rho(5)] -> 5 (relu) -> 5
        // carry rinv_new = 1/sigma_new = exp(-relu(out))
        float hs[Kn];
#pragma unroll
        for (int o = 0; o < Kn; o++) {
            const int base = SG_W1 + o * 23;
            float a = cw[SG_B1 + o];
#pragma unroll
            for (int c = 0; c < Cn; c++)  a = fmaf(cw[base + c],      x[c],   a);
#pragma unroll
            for (int i = 0; i < CKn; i++) a = fmaf(cw[base + 3 + i],  mun[i], a);
#pragma unroll
            for (int i = 0; i < Kn; i++)  a = fmaf(cw[base + 18 + i], rho[i], a);
            hs[o] = fmaxf(a, 0.f);
        }
        float rin[Kn];
#pragma unroll
        for (int o = 0; o < Kn; o++) {
            float a = cw[SG_B2 + o];
#pragma unroll
            for (int i = 0; i < Kn; i++) a = fmaf(cw[SG_W2 + o * 5 + i], hs[i], a);
            rin[o] = __expf(-fmaxf(a, 0.f));
        }

        // ---- density 2 (mu_new, sigma_new), gamma input g = pi_new*dens2
        float g[Kn];
#pragma unroll
        for (int k = 0; k < Kn; k++) {
            const float r  = rin[k];
            const float r2 = r * r;
            float d = 0.f;
#pragma unroll
            for (int c = 0; c < Cn; c++) {
                const float t = x[c] - mun[k * Cn + c];
                d = fmaf(t, t, d);
            }
            const float dens2 = C0 * r2 * r * __expf(-0.5f * d * r2);
            g[k] = pin[k] * dens2;
        }

        // ---- gamma MLP: 5 -> 5 (relu) -> 1, sigmoid --------------------
        float hg[Kn];
#pragma unroll
        for (int o = 0; o < Kn; o++) {
            float a = cw[GA_B1 + o];
#pragma unroll
            for (int i = 0; i < Kn; i++) a = fmaf(cw[GA_W1 + o * 5 + i], g[i], a);
            hg[o] = fmaxf(a, 0.f);
        }
        float ga = cw[GA_B2];
#pragma unroll
        for (int i = 0; i < Kn; i++) ga = fmaf(cw[GA_W2 + i], hg[i], ga);

        ob[s * HWn] = sigmoid_f(ga);

        // ---- carry ------------------------------------------------------
#pragma unroll
        for (int k = 0; k < Kn; k++) { pi[k] = pin[k]; ri[k] = rin[k]; }
#pragma unroll
        for (int i = 0; i < CKn; i++) mu[i] = mun[i];
    }
}

extern "C" void kernel_launch(void* const* d_in, const int* in_sizes, int n_in,
                              void* d_out, int out_size)
{
    (void)in_sizes; (void)n_in; (void)out_size;
    const float* frames = (const float*)d_in[0];
    // d_in[1] = targets (unused by reference output path)
    const float* mu0 = (const float*)d_in[2];

    struct Cp { int idx; int off; int n; };
    const Cp cps[16] = {
        {3,  PI_W1, 50},  {4,  PI_B1, 5},  {5,  PI_W2, 25},  {6,  PI_B2, 5},
        {7,  MU_W1, 345}, {8,  MU_B1, 15}, {9,  MU_W2, 225}, {10, MU_B2, 15},
        {11, SG_W1, 115}, {12, SG_B1, 5},  {13, SG_W2, 25},  {14, SG_B2, 5},
        {15, GA_W1, 25},  {16, GA_B1, 5},  {17, GA_W2, 5},   {18, GA_B2, 1},
    };
    for (int i = 0; i < 16; i++) {
        cudaMemcpyToSymbolAsync(cw, d_in[cps[i].idx],
                                (size_t)cps[i].n * sizeof(float),
                                (size_t)cps[i].off * sizeof(float),
                                cudaMemcpyDeviceToDevice, 0);
    }

    const int threads = 256;
    const int blocks  = (NPIX + threads - 1) / threads;  // 2304
    gmm_kernel<<<blocks, threads>>>(frames, mu0, (float*)d_out);
}

// round 2
// speedup vs baseline: 1.5662x; 1.5662x over previous
#include <cuda_runtime.h>

// ---------------------------------------------------------------------------
// GMMNet, 2 pixels per thread via packed f32x2 (FFMA2) arithmetic.
// Weights are duplicated into {w,w} 64-bit pairs in __constant__ memory so the
// MAC stream is LDCU.64 + FFMA2 (2 MACs per issue slot).
// ---------------------------------------------------------------------------

typedef unsigned long long u64;

namespace {
constexpr int Bn = 4, Sn = 8, Cn = 3, Hn = 384, Wn = 384, Kn = 5, CKn = 15;
constexpr int HWn  = Hn * Wn;            // 147456
constexpr int NPIX = Bn * HWn;           // 589824
constexpr int HALF = NPIX / 2;           // 294912

// constant-bank layout (element offsets, ascending)
constexpr int PI_W1 = 0,   PI_B1 = 50,  PI_W2 = 55,  PI_B2 = 80;
constexpr int MU_W1 = 85,  MU_B1 = 430, MU_W2 = 445, MU_B2 = 670;
constexpr int SG_W1 = 685, SG_B1 = 800, SG_W2 = 805, SG_B2 = 830;
constexpr int GA_W1 = 835, GA_B1 = 860, GA_W2 = 865, GA_B2 = 870;
constexpr int NWTS  = 871;
}

__constant__ u64 cw2[NWTS];          // duplicated {w,w} pairs
__device__   u64 g_staging[NWTS];    // staging for capturable copy-to-constant

// ---- packed f32x2 helpers --------------------------------------------------
__device__ __forceinline__ u64 pk(float lo, float hi) {
    u64 r; asm("mov.b64 %0, {%1, %2};" : "=l"(r) : "f"(lo), "f"(hi)); return r;
}
__device__ __forceinline__ void upk(u64 v, float& lo, float& hi) {
    asm("mov.b64 {%0, %1}, %2;" : "=f"(lo), "=f"(hi) : "l"(v));
}
__device__ __forceinline__ u64 fma2(u64 a, u64 b, u64 c) {
    u64 d; asm("fma.rn.f32x2 %0, %1, %2, %3;" : "=l"(d) : "l"(a), "l"(b), "l"(c)); return d;
}
__device__ __forceinline__ u64 mul2(u64 a, u64 b) {
    u64 d; asm("mul.rn.f32x2 %0, %1, %2;" : "=l"(d) : "l"(a), "l"(b)); return d;
}
__device__ __forceinline__ u64 add2(u64 a, u64 b) {
    u64 d; asm("add.rn.f32x2 %0, %1, %2;" : "=l"(d) : "l"(a), "l"(b)); return d;
}
__device__ __forceinline__ float ex2f(float x) {
    float y; asm("ex2.approx.f32 %0, %1;" : "=f"(y) : "f"(x)); return y;
}
__device__ __forceinline__ float rcpf(float x) {
    float y; asm("rcp.approx.f32 %0, %1;" : "=f"(y) : "f"(x)); return y;
}
// ex2 applied per half
__device__ __forceinline__ u64 ex2_2(u64 x) {
    float lo, hi; upk(x, lo, hi); return pk(ex2f(lo), ex2f(hi));
}
// exact relu: 0.5*(x + |x|)   (|x| = clear sign bits; exact for our ranges)
__device__ __forceinline__ u64 relu2(u64 x) {
    const u64 ax = x & 0x7fffffff7fffffffULL;
    return mul2(add2(x, ax), 0x3f0000003f000000ULL /* {0.5f,0.5f} */);
}

// ---- weight duplication kernel ----------------------------------------------
struct WPtrs { const float* p[16]; };

__global__ void dup_weights(WPtrs w) {
    const int i = blockIdx.x * blockDim.x + threadIdx.x;
    if (i >= NWTS) return;
    constexpr int off[17] = {PI_W1, PI_B1, PI_W2, PI_B2,
                             MU_W1, MU_B1, MU_W2, MU_B2,
                             SG_W1, SG_B1, SG_W2, SG_B2,
                             GA_W1, GA_B1, GA_W2, GA_B2, NWTS};
    int s = 0;
#pragma unroll
    for (int k = 1; k < 16; k++) if (i >= off[k]) s = k;
    const float v = w.p[s][i - off[s]];
    g_staging[i] = pk(v, v);
}

// ---- main kernel -------------------------------------------------------------
__global__ void __launch_bounds__(256)
gmm2_kernel(const float* __restrict__ frames,   // [B,S,C,H,W]
            const float* __restrict__ mu0,      // [B,CK,H,W]
            float* __restrict__ out)            // [B,S,1,H,W]
{
    const int t = blockIdx.x * blockDim.x + threadIdx.x;
    if (t >= HALF) return;

    // lane pair: pixel t (lo) and pixel t+HALF (hi)
    const int b0 = t / HWn,          hw0 = t - b0 * HWn;
    const int p1 = t + HALF;
    const int b1 = p1 / HWn,         hw1 = p1 - b1 * HWn;

    const float* f0 = frames + (b0 * Sn * Cn) * HWn + hw0;
    const float* f1 = frames + (b1 * Sn * Cn) * HWn + hw1;
    const float* m0 = mu0 + (b0 * CKn) * HWn + hw0;
    const float* m1 = mu0 + (b1 * CKn) * HWn + hw1;
    float* o0 = out + (b0 * Sn) * HWn + hw0;
    float* o1 = out + (b1 * Sn) * HWn + hw1;

    const float L2E  = 1.4426950408889634f;
    const u64 LOG2E2  = pk(L2E, L2E);
    const u64 NL2E2   = pk(-L2E, -L2E);
    const u64 NHL2E2  = pk(-0.7213475204444817f, -0.7213475204444817f); // -0.5*log2e
    const u64 ONE2    = pk(1.0f, 1.0f);
    const u64 NEG12   = pk(-1.0f, -1.0f);
    const u64 C02     = pk(0.06349363593424097f, 0.06349363593424097f); // (2pi)^-1.5

    // carried state (packed)
    u64 pi[Kn], mu[CKn], ri[Kn];
#pragma unroll
    for (int k = 0; k < Kn; k++) { pi[k] = pk(0.2f, 0.2f); ri[k] = ONE2; }
#pragma unroll
    for (int i = 0; i < CKn; i++) mu[i] = pk(m0[i * HWn], m1[i * HWn]);

    for (int s = 0; s < Sn; s++) {
        u64 x[Cn];
#pragma unroll
        for (int c = 0; c < Cn; c++)
            x[c] = pk(f0[(s * Cn + c) * HWn], f1[(s * Cn + c) * HWn]);

        // ---- density 1, alpha, rho ---------------------------------------
        u64 alpha[Kn], rho[Kn];
#pragma unroll
        for (int k = 0; k < Kn; k++) {
            const u64 r  = ri[k];
            const u64 r2 = mul2(r, r);
            u64 t0 = fma2(mu[k * Cn + 0], NEG12, x[0]);
            u64 d  = mul2(t0, t0);
            u64 t1 = fma2(mu[k * Cn + 1], NEG12, x[1]);
            d = fma2(t1, t1, d);
            u64 t2 = fma2(mu[k * Cn + 2], NEG12, x[2]);
            d = fma2(t2, t2, d);
            const u64 e    = ex2_2(mul2(mul2(d, r2), NHL2E2));
            const u64 coef = mul2(mul2(r, C02), r2);       // C0 * r^3
            const u64 dens = mul2(coef, e);
            alpha[k] = mul2(pi[k], dens);
            rho[k]   = mul2(alpha[k], dens);
        }

        // ---- pi MLP: [pi(5), alpha(5)] -> 5 relu -> 5, softmax ------------
        u64 hp[Kn];
#pragma unroll
        for (int o = 0; o < Kn; o++) {
            u64 a = cw2[PI_B1 + o];
#pragma unroll
            for (int i = 0; i < Kn; i++) a = fma2(cw2[PI_W1 + o * 10 + i],     pi[i],    a);
#pragma unroll
            for (int i = 0; i < Kn; i++) a = fma2(cw2[PI_W1 + o * 10 + 5 + i], alpha[i], a);
            hp[o] = relu2(a);
        }
        u64 pin[Kn], esum = 0ULL;
#pragma unroll
        for (int o = 0; o < Kn; o++) {
            u64 a = cw2[PI_B2 + o];
#pragma unroll
            for (int i = 0; i < Kn; i++) a = fma2(cw2[PI_W2 + o * 5 + i], hp[i], a);
            pin[o] = ex2_2(mul2(a, LOG2E2));
            esum   = add2(esum, pin[o]);
        }
        {
            float el, eh; upk(esum, el, eh);
            const u64 einv = pk(rcpf(el), rcpf(eh));
#pragma unroll
            for (int k = 0; k < Kn; k++) pin[k] = mul2(pin[k], einv);
        }

        // ---- mu MLP: [x(3), mu(15), rho(5)] -> 15 relu -> 15, sigmoid ----
        u64 hm[CKn];
#pragma unroll
        for (int o = 0; o < CKn; o++) {
            const int base = MU_W1 + o * 23;
            u64 a = cw2[MU_B1 + o];
#pragma unroll
            for (int c = 0; c < Cn; c++)  a = fma2(cw2[base + c],      x[c],   a);
#pragma unroll
            for (int i = 0; i < CKn; i++) a = fma2(cw2[base + 3 + i],  mu[i],  a);
#pragma unroll
            for (int i = 0; i < Kn; i++)  a = fma2(cw2[base + 18 + i], rho[i], a);
            hm[o] = relu2(a);
        }
        u64 mun[CKn];
#pragma unroll
        for (int o = 0; o < CKn; o++) {
            u64 a = cw2[MU_B2 + o];
#pragma unroll
            for (int i = 0; i < CKn; i++) a = fma2(cw2[MU_W2 + o * 15 + i], hm[i], a);
            // sigmoid: 1 / (1 + exp(-a))
            const u64 den = add2(ex2_2(mul2(a, NL2E2)), ONE2);
            float dl, dh; upk(den, dl, dh);
            mun[o] = pk(rcpf(dl), rcpf(dh));
        }

        // ---- sigma MLP: [x(3), mun(15), rho(5)] -> 5 relu -> 5 -----------
        // carry rinv_new = exp(-relu(out))
        u64 hs[Kn];
#pragma unroll
        for (int o = 0; o < Kn; o++) {
            const int base = SG_W1 + o * 23;
            u64 a = cw2[SG_B1 + o];
#pragma unroll
            for (int c = 0; c < Cn; c++)  a = fma2(cw2[base + c],      x[c],   a);
#pragma unroll
            for (int i = 0; i < CKn; i++) a = fma2(cw2[base + 3 + i],  mun[i], a);
#pragma unroll
            for (int i = 0; i < Kn; i++)  a = fma2(cw2[base + 18 + i], rho[i], a);
            hs[o] = relu2(a);
        }
        u64 rin[Kn];
#pragma unroll
        for (int o = 0; o < Kn; o++) {
            u64 a = cw2[SG_B2 + o];
#pragma unroll
            for (int i = 0; i < Kn; i++) a = fma2(cw2[SG_W2 + o * 5 + i], hs[i], a);
            rin[o] = ex2_2(mul2(relu2(a), NL2E2));
        }

        // ---- density 2, g = pi_new * dens2 --------------------------------
        u64 g[Kn];
#pragma unroll
        for (int k = 0; k < Kn; k++) {
            const u64 r  = rin[k];
            const u64 r2 = mul2(r, r);
            u64 t0 = fma2(mun[k * Cn + 0], NEG12, x[0]);
            u64 d  = mul2(t0, t0);
            u64 t1 = fma2(mun[k * Cn + 1], NEG12, x[1]);
            d = fma2(t1, t1, d);
            u64 t2 = fma2(mun[k * Cn + 2], NEG12, x[2]);
            d = fma2(t2, t2, d);
            const u64 e    = ex2_2(mul2(mul2(d, r2), NHL2E2));
            const u64 coef = mul2(mul2(r, C02), r2);
            g[k] = mul2(pin[k], mul2(coef, e));
        }

        // ---- gamma MLP: 5 -> 5 relu -> 1, sigmoid -------------------------
        u64 hg[Kn];
#pragma unroll
        for (int o = 0; o < Kn; o++) {
            u64 a = cw2[GA_B1 + o];
#pragma unroll
            for (int i = 0; i < Kn; i++) a = fma2(cw2[GA_W1 + o * 5 + i], g[i], a);
            hg[o] = relu2(a);
        }
        u64 ga = cw2[GA_B2];
#pragma unroll
        for (int i = 0; i < Kn; i++) ga = fma2(cw2[GA_W2 + i], hg[i], ga);

        {
            float gl, gh; upk(ga, gl, gh);
            o0[s * HWn] = rcpf(1.0f + ex2f(-L2E * gl));
            o1[s * HWn] = rcpf(1.0f + ex2f(-L2E * gh));
        }

        // ---- carry --------------------------------------------------------
#pragma unroll
        for (int k = 0; k < Kn; k++) { pi[k] = pin[k]; ri[k] = rin[k]; }
#pragma unroll
        for (int i = 0; i < CKn; i++) mu[i] = mun[i];
    }
}

extern "C" void kernel_launch(void* const* d_in, const int* in_sizes, int n_in,
                              void* d_out, int out_size)
{
    (void)in_sizes; (void)n_in; (void)out_size;
    const float* frames = (const float*)d_in[0];
    const float* mu0    = (const float*)d_in[2];   // d_in[1] = targets (unused)

    WPtrs w;
    for (int i = 0; i < 16; i++) w.p[i] = (const float*)d_in[3 + i];

    dup_weights<<<4, 256>>>(w);

    void* staging_addr = nullptr;
    cudaGetSymbolAddress(&staging_addr, g_staging);
    cudaMemcpyToSymbolAsync(cw2, staging_addr, NWTS * sizeof(u64), 0,
                            cudaMemcpyDeviceToDevice, 0);

    const int threads = 256;
    const int blocks  = HALF / threads;   // 1152
    gmm2_kernel<<<blocks, threads>>>(frames, mu0, (float*)d_out);
}